// round 15
// baseline (speedup 1.0000x reference)
#include <cuda_runtime.h>

// Problem constants (match reference)
#define BATCH   512
#define IN_DIM  784
#define OUT_DIM 10
#define STEPS   200
#define NSCAN   (STEPS - 1)              // 199 drive entries / scan steps
#define TC      32                       // time-chunk size
#define NCHUNK  ((NSCAN + TC - 1) / TC)  // 7
#define NG      16                       // i-groups (one warp each)
#define IPG     (IN_DIM / NG)            // 49 inputs per warp

// LIF constants
#define A_M     0.995f                   // 1 - DT/TAU_M
#define G_M     0.005f                   // DT/TAU_M
#define A_S     0.98f                    // 1 - DT/TAU_S

__device__ __forceinline__ float ldg(const float* p) {
    float v;
    asm volatile("ld.global.f32 %0, [%1];" : "=f"(v) : "l"(p));
    return v;
}

__global__ __launch_bounds__(512, 4)
void snn_kernel(const float* __restrict__ x,     // [B, IN, STEPS]
                const float* __restrict__ w,     // [O, IN]
                float* __restrict__ out)         // [B, O]
{
    __shared__ __align__(16) float wsh[OUT_DIM * IN_DIM]; // [o][i] (gmem layout), 31360 B
    __shared__ float drvp[NG][TC * OUT_DIM];              // 16 partials, 20480 B
    __shared__ int   done_sh;

    const int b   = blockIdx.x;
    const int tid = threadIdx.x;
    const int g   = tid >> 5;            // warp id = i-group
    const int tl  = tid & 31;            // lane = t within chunk

    // Weights: pure coalesced float4 copy, identical layout in smem.
    {
        const float4* w4  = (const float4*)w;
        float4*       ws4 = (float4*)wsh;
        #pragma unroll
        for (int k = tid; k < (OUT_DIM * IN_DIM) / 4; k += 512)
            ws4[k] = w4[k];
    }
    if (tid == 0) done_sh = 0;
    // No sync here — the sync before first consume covers it.

    const float* xb = x + (size_t)b * IN_DIM * STEPS;

    // LIF state for threads 0..9 (persists across chunks)
    float V = 0.0f, I = 0.0f;
    int   fst = 0;
    const int ibase = g * IPG;

    for (int c = 0; c < NCHUNK; c++) {
        const int t0   = c * TC;
        const int tcur = t0 + tl;        // drive index this lane computes

        // ---- Phase A: 49 loads, each consumed immediately (no batching).
        //      Fully unrolled so ptxas pipelines LDGs up to the register budget.
        unsigned m0 = 0u, m1 = 0u;       // bit j -> i = ibase + j (m1: j+32)
        if (tcur < NSCAN) {
            const float* xp = xb + (size_t)ibase * STEPS + tcur;
            #pragma unroll
            for (int i0 = 0; i0 < 32; i0++) {
                float v = ldg(xp + (size_t)i0 * STEPS);
                unsigned nz = (__float_as_uint(v) != 0u) ? 1u : 0u;
                m0 |= nz << i0;
            }
            #pragma unroll
            for (int i0 = 32; i0 < IPG; i0++) {
                float v = ldg(xp + (size_t)i0 * STEPS);
                unsigned nz = (__float_as_uint(v) != 0u) ? 1u : 0u;
                m1 |= nz << (i0 - 32);
            }
        }

        if (c == 0) __syncthreads();     // uniform; weights now visible

        // ---- Phase B: dense mask walk (~1 set bit/thread on average) ----
        float acc[OUT_DIM];
        #pragma unroll
        for (int o = 0; o < OUT_DIM; o++) acc[o] = 0.0f;
        while (m0) {
            int j = __ffs(m0) - 1;
            m0 &= m0 - 1;
            const float* wr = &wsh[ibase + j];
            #pragma unroll
            for (int o = 0; o < OUT_DIM; o++) acc[o] += wr[o * IN_DIM];
        }
        while (m1) {
            int j = __ffs(m1) - 1;
            m1 &= m1 - 1;
            const float* wr = &wsh[ibase + 32 + j];
            #pragma unroll
            for (int o = 0; o < OUT_DIM; o++) acc[o] += wr[o * IN_DIM];
        }

        // ---- single-pass reduce: 16 partials summed by 320 threads ----
        {
            float* dp = &drvp[g][tl * OUT_DIM];
            #pragma unroll
            for (int o = 0; o < OUT_DIM; o++) dp[o] = acc[o];
        }
        __syncthreads();
        if (tid < TC * OUT_DIM) {        // 320 threads: one (t,o) each
            float s = drvp[0][tid];
            #pragma unroll
            for (int q = 1; q < NG; q++) s += drvp[q][tid];
            drvp[0][tid] = s;
        }
        __syncthreads();

        // ---- incremental LIF scan by threads 0..9 ----
        if (tid < OUT_DIM) {
            const int o    = tid;
            const int tend = min(TC, NSCAN - t0);
            if (fst == 0) {
                for (int tt = 0; tt < tend; tt++) {
                    float Vn = A_M * V + G_M * I;
                    float In = A_S * I + drvp[0][tt * OUT_DIM + o];
                    if (Vn > 1.0f) { fst = t0 + tt + 1; break; }
                    V = Vn;
                    I = In;
                }
            }
            unsigned m = __ballot_sync(0x3FFu, fst != 0);
            if (tid == 0 && m == 0x3FFu) done_sh = 1;
        }
        __syncthreads();
        if (done_sh) break;              // all 10 neurons spiked: rest of x[b] is dead
    }

    if (tid < OUT_DIM)
        out[b * OUT_DIM + tid] = (fst == 0) ? (float)(STEPS - 1) : (float)fst;
}

extern "C" void kernel_launch(void* const* d_in, const int* in_sizes, int n_in,
                              void* d_out, int out_size)
{
    const float* x = (const float*)d_in[0];   // [512, 784, 200]
    const float* w = (const float*)d_in[1];   // [10, 784]
    float* out = (float*)d_out;               // [512, 10]
    snn_kernel<<<BATCH, 512>>>(x, w, out);
}

// round 16
// speedup vs baseline: 1.1468x; 1.1468x over previous
#include <cuda_runtime.h>

// Problem constants (match reference)
#define BATCH   512
#define IN_DIM  784
#define OUT_DIM 10
#define STEPS   200
#define NSCAN   (STEPS - 1)              // 199 drive entries / scan steps
#define TC      32                       // time-chunk size
#define NCHUNK  ((NSCAN + TC - 1) / TC)  // 7
#define NG      16                       // i-groups (one warp each)
#define IPG     (IN_DIM / NG)            // 49 inputs per warp

// LIF constants
#define A_M     0.995f                   // 1 - DT/TAU_M
#define G_M     0.005f                   // DT/TAU_M
#define A_S     0.98f                    // 1 - DT/TAU_S

__device__ __forceinline__ float ldg(const float* p) {
    float v;
    asm volatile("ld.global.f32 %0, [%1];" : "=f"(v) : "l"(p));
    return v;
}

__global__ __launch_bounds__(512, 4)
void snn_kernel(const float* __restrict__ x,     // [B, IN, STEPS]
                const float* __restrict__ w,     // [O, IN]
                float* __restrict__ out)         // [B, O]
{
    __shared__ __align__(16) float wsh[OUT_DIM * IN_DIM]; // [o][i] (gmem layout), 31360 B
    __shared__ float drvp[8][TC * OUT_DIM];               // partial drives, 10240 B
    __shared__ float drvs[OUT_DIM * TC];                  // summed drive [o][t], 1280 B
    __shared__ float Ktab[TC];                            // LIF kernel K(d), 128 B
    __shared__ int   fst_sh[OUT_DIM];
    __shared__ int   done_sh;

    const int b   = blockIdx.x;
    const int tid = threadIdx.x;
    const int g   = tid >> 5;            // warp id = i-group
    const int tl  = tid & 31;            // lane = t within chunk

    // Weights: pure coalesced float4 copy, identical layout in smem.
    {
        const float4* w4  = (const float4*)w;
        float4*       ws4 = (float4*)wsh;
        #pragma unroll
        for (int k = tid; k < (OUT_DIM * IN_DIM) / 4; k += 512)
            ws4[k] = w4[k];
    }
    if (tid == 0) {
        done_sh = 0;
        // Exact K table: K(d) = G_M * P(d), P(d) = A_M*P(d-1) + A_S^d
        float P = 1.0f, As = 1.0f;       // P(0)=1, A_S^0=1
        Ktab[0] = G_M * P;
        for (int d = 1; d < TC; d++) {
            As *= A_S;
            P = A_M * P + As;
            Ktab[d] = G_M * P;
        }
    }
    // No sync here — the sync before first consume covers it.

    const float* xb = x + (size_t)b * IN_DIM * STEPS;

    // LIF state (used only on the rare fallback path)
    float V = 0.0f, I = 0.0f;
    int   fst = 0;
    const int ibase = g * IPG;

    // ================= chunk 0 (common case: everything resolves here) ====
    {
        // ---- Phase A: stream x[b, ibase..ibase+48, tl] into a 49-bit mask ----
        unsigned m0 = 0u, m1 = 0u;
        {
            const float* xp = xb + (size_t)ibase * STEPS + tl;
            #pragma unroll 1
            for (int i0 = 0; i0 < IPG; i0 += 7) {     // 49 = 7 x 7
                float v[7];
                #pragma unroll
                for (int j = 0; j < 7; j++)
                    v[j] = ldg(xp + (size_t)(i0 + j) * STEPS);
                #pragma unroll
                for (int j = 0; j < 7; j++) {
                    unsigned nz = (__float_as_uint(v[j]) != 0u) ? 1u : 0u;
                    int bit = i0 + j;
                    if (bit < 32) m0 |= nz << bit;
                    else          m1 |= nz << (bit - 32);
                }
            }
        }

        __syncthreads();                 // weights + Ktab visible

        // ---- Phase B: dense mask walk ----
        float acc[OUT_DIM];
        #pragma unroll
        for (int o = 0; o < OUT_DIM; o++) acc[o] = 0.0f;
        while (m0) {
            int j = __ffs(m0) - 1;
            m0 &= m0 - 1;
            const float* wr = &wsh[ibase + j];
            #pragma unroll
            for (int o = 0; o < OUT_DIM; o++) acc[o] += wr[o * IN_DIM];
        }
        while (m1) {
            int j = __ffs(m1) - 1;
            m1 &= m1 - 1;
            const float* wr = &wsh[ibase + 32 + j];
            #pragma unroll
            for (int o = 0; o < OUT_DIM; o++) acc[o] += wr[o * IN_DIM];
        }

        // ---- reduce 16 -> 8 -> 1 into drvs[o][t] ----
        float* dp = &drvp[g & 7][tl * OUT_DIM];
        if (g >= 8) {
            #pragma unroll
            for (int o = 0; o < OUT_DIM; o++) dp[o] = acc[o];
        }
        __syncthreads();
        if (g < 8) {
            #pragma unroll
            for (int o = 0; o < OUT_DIM; o++) dp[o] += acc[o];
        }
        __syncthreads();
        if (tid < TC * OUT_DIM) {        // thread = (o, tt): warp-per-o layout
            const int o  = tid >> 5;
            const int tt = tid & 31;
            float s = drvp[0][tt * OUT_DIM + o];
            #pragma unroll
            for (int q = 1; q < 8; q++) s += drvp[q][tt * OUT_DIM + o];
            drvs[o * TC + tt] = s;
        }
        __syncthreads();

        // ---- PARALLEL first-spike: lane tt of warp o evaluates Vn(tt) ----
        if (tid < TC * OUT_DIM) {
            const int o  = tid >> 5;
            const int tt = tid & 31;
            const float* dro = &drvs[o * TC];
            float Vn = 0.0f;
            #pragma unroll
            for (int u = 0; u < TC - 1; u++)           // u < tt <= 31
                if (u < tt) Vn += Ktab[tt - 1 - u] * dro[u];
            unsigned bal = __ballot_sync(0xFFFFFFFFu, Vn > 1.0f);
            if (tt == 0) fst_sh[o] = bal ? __ffs(bal) : 0;  // spike step +1, 0 if none
        }
        __syncthreads();
        if (tid < OUT_DIM) {
            fst = fst_sh[tid];
            unsigned m = __ballot_sync(0x3FFu, fst != 0);
            if (tid == 0) done_sh = (m == 0x3FFu);
        }
        __syncthreads();
    }

    // ================= rare fallback: chunks 1..6 with serial scan =========
    if (!done_sh) {
        // Re-establish carried (V, I) at end of chunk 0 serially (cheap, rare).
        if (tid < OUT_DIM) {
            const float* dro = &drvs[tid * TC];
            V = 0.0f; I = 0.0f;
            for (int tt = 0; tt < TC; tt++) {
                float Vn = A_M * V + G_M * I;
                float In = A_S * I + dro[tt];
                if (fst == 0 && Vn > 1.0f) { fst = tt + 1; }
                if (fst == 0) { V = Vn; I = In; } else break;
            }
        }
        for (int c = 1; c < NCHUNK; c++) {
            const int t0   = c * TC;
            const int tcur = t0 + tl;

            unsigned m0 = 0u, m1 = 0u;
            if (tcur < NSCAN) {
                const float* xp = xb + (size_t)ibase * STEPS + tcur;
                #pragma unroll 1
                for (int i0 = 0; i0 < IPG; i0 += 7) {
                    float v[7];
                    #pragma unroll
                    for (int j = 0; j < 7; j++)
                        v[j] = ldg(xp + (size_t)(i0 + j) * STEPS);
                    #pragma unroll
                    for (int j = 0; j < 7; j++) {
                        unsigned nz = (__float_as_uint(v[j]) != 0u) ? 1u : 0u;
                        int bit = i0 + j;
                        if (bit < 32) m0 |= nz << bit;
                        else          m1 |= nz << (bit - 32);
                    }
                }
            }

            float acc[OUT_DIM];
            #pragma unroll
            for (int o = 0; o < OUT_DIM; o++) acc[o] = 0.0f;
            while (m0) {
                int j = __ffs(m0) - 1;
                m0 &= m0 - 1;
                const float* wr = &wsh[ibase + j];
                #pragma unroll
                for (int o = 0; o < OUT_DIM; o++) acc[o] += wr[o * IN_DIM];
            }
            while (m1) {
                int j = __ffs(m1) - 1;
                m1 &= m1 - 1;
                const float* wr = &wsh[ibase + 32 + j];
                #pragma unroll
                for (int o = 0; o < OUT_DIM; o++) acc[o] += wr[o * IN_DIM];
            }

            float* dp = &drvp[g & 7][tl * OUT_DIM];
            if (g >= 8) {
                #pragma unroll
                for (int o = 0; o < OUT_DIM; o++) dp[o] = acc[o];
            }
            __syncthreads();
            if (g < 8) {
                #pragma unroll
                for (int o = 0; o < OUT_DIM; o++) dp[o] += acc[o];
            }
            __syncthreads();
            if (tid < TC * OUT_DIM) {
                const int o  = tid >> 5;
                const int tt = tid & 31;
                float s = drvp[0][tt * OUT_DIM + o];
                #pragma unroll
                for (int q = 1; q < 8; q++) s += drvp[q][tt * OUT_DIM + o];
                drvs[o * TC + tt] = s;
            }
            __syncthreads();

            if (tid < OUT_DIM) {
                const int o    = tid;
                const int tend = min(TC, NSCAN - t0);
                if (fst == 0) {
                    const float* dro = &drvs[o * TC];
                    for (int tt = 0; tt < tend; tt++) {
                        float Vn = A_M * V + G_M * I;
                        float In = A_S * I + dro[tt];
                        if (Vn > 1.0f) { fst = t0 + tt + 1; break; }
                        V = Vn;
                        I = In;
                    }
                }
                unsigned m = __ballot_sync(0x3FFu, fst != 0);
                if (tid == 0 && m == 0x3FFu) done_sh = 1;
            }
            __syncthreads();
            if (done_sh) break;
        }
    }

    if (tid < OUT_DIM)
        out[b * OUT_DIM + tid] = (fst == 0) ? (float)(STEPS - 1) : (float)fst;
}

extern "C" void kernel_launch(void* const* d_in, const int* in_sizes, int n_in,
                              void* d_out, int out_size)
{
    const float* x = (const float*)d_in[0];   // [512, 784, 200]
    const float* w = (const float*)d_in[1];   // [10, 784]
    float* out = (float*)d_out;               // [512, 10]
    snn_kernel<<<BATCH, 512>>>(x, w, out);
}

// round 17
// speedup vs baseline: 1.3441x; 1.1721x over previous
#include <cuda_runtime.h>

// Problem constants (match reference)
#define BATCH   512
#define IN_DIM  784
#define OUT_DIM 10
#define STEPS   200
#define NSCAN   (STEPS - 1)              // 199 drive entries / scan steps
#define TC      32                       // time-chunk size
#define NCHUNK  ((NSCAN + TC - 1) / TC)  // 7
#define NG      16                       // i-groups (one warp each)
#define IPG     (IN_DIM / NG)            // 49 inputs per warp = 7 batches of 7

// LIF constants
#define A_M     0.995f                   // 1 - DT/TAU_M
#define G_M     0.005f                   // DT/TAU_M
#define A_S     0.98f                    // 1 - DT/TAU_S

__device__ __forceinline__ float ldg(const float* p) {
    float v;
    asm volatile("ld.global.f32 %0, [%1];" : "=f"(v) : "l"(p));
    return v;
}

// 3 CTAs/SM: trades ~10% occupancy for 2x per-warp MLP (reg budget ~42).
__global__ __launch_bounds__(512, 3)
void snn_kernel(const float* __restrict__ x,     // [B, IN, STEPS]
                const float* __restrict__ w,     // [O, IN]
                float* __restrict__ out)         // [B, O]
{
    __shared__ __align__(16) float wsh[OUT_DIM * IN_DIM]; // [o][i] (gmem layout), 31360 B
    __shared__ float drvp[8][TC * OUT_DIM];               // partial drives, 10240 B
    __shared__ int   done_sh;

    const int b   = blockIdx.x;
    const int tid = threadIdx.x;
    const int g   = tid >> 5;            // warp id = i-group
    const int tl  = tid & 31;            // lane = t within chunk

    // Weights: pure coalesced float4 copy, identical layout in smem.
    {
        const float4* w4  = (const float4*)w;
        float4*       ws4 = (float4*)wsh;
        #pragma unroll
        for (int k = tid; k < (OUT_DIM * IN_DIM) / 4; k += 512)
            ws4[k] = w4[k];
    }
    if (tid == 0) done_sh = 0;
    // No sync here — the sync before first consume covers it.

    const float* xb = x + (size_t)b * IN_DIM * STEPS;

    // LIF state for threads 0..9 (persists across chunks)
    float V = 0.0f, I = 0.0f;
    int   fst = 0;
    const int ibase = g * IPG;

    for (int c = 0; c < NCHUNK; c++) {
        const int t0   = c * TC;
        const int tcur = t0 + tl;        // drive index this lane computes

        // ---- Phase A: stream x[b, ibase..ibase+48, tcur] into a 49-bit mask.
        //      Double-buffered 7-load batches: ~14 loads in flight per warp.
        unsigned m0 = 0u, m1 = 0u;       // bit j -> i = ibase + j (m1: j+32)
        if (tcur < NSCAN) {
            const float* xp = xb + (size_t)ibase * STEPS + tcur;
            float vA[7], vB[7];

            #define LOADB(V, K)                                           \
                do {                                                      \
                    const float* bp_ = xp + (size_t)((K) * 7) * STEPS;    \
                    _Pragma("unroll")                                     \
                    for (int j = 0; j < 7; j++)                           \
                        (V)[j] = ldg(bp_ + (size_t)j * STEPS);            \
                } while (0)

            #define MASKB(V, K)                                           \
                do {                                                      \
                    _Pragma("unroll")                                     \
                    for (int j = 0; j < 7; j++) {                         \
                        unsigned nz = (__float_as_uint((V)[j]) != 0u);    \
                        int bit = (K) * 7 + j;                            \
                        if (bit < 32) m0 |= nz << bit;                    \
                        else          m1 |= nz << (bit - 32);             \
                    }                                                     \
                } while (0)

            LOADB(vA, 0);
            LOADB(vB, 1);                // 14 loads now in flight
            MASKB(vA, 0);
            LOADB(vA, 2);
            MASKB(vB, 1);
            LOADB(vB, 3);
            MASKB(vA, 2);
            LOADB(vA, 4);
            MASKB(vB, 3);
            LOADB(vB, 5);
            MASKB(vA, 4);
            LOADB(vA, 6);
            MASKB(vB, 5);
            MASKB(vA, 6);

            #undef LOADB
            #undef MASKB
        }

        if (c == 0) __syncthreads();     // uniform; weights now visible

        // ---- Phase B: dense mask walk (~1 set bit/thread on average) ----
        float acc[OUT_DIM];
        #pragma unroll
        for (int o = 0; o < OUT_DIM; o++) acc[o] = 0.0f;
        while (m0) {
            int j = __ffs(m0) - 1;
            m0 &= m0 - 1;
            const float* wr = &wsh[ibase + j];
            #pragma unroll
            for (int o = 0; o < OUT_DIM; o++) acc[o] += wr[o * IN_DIM];
        }
        while (m1) {
            int j = __ffs(m1) - 1;
            m1 &= m1 - 1;
            const float* wr = &wsh[ibase + 32 + j];
            #pragma unroll
            for (int o = 0; o < OUT_DIM; o++) acc[o] += wr[o * IN_DIM];
        }

        // ---- reduce 16 partials -> 8 -> 1 ----
        float* dp = &drvp[g & 7][tl * OUT_DIM];
        if (g >= 8) {
            #pragma unroll
            for (int o = 0; o < OUT_DIM; o++) dp[o] = acc[o];
        }
        __syncthreads();
        if (g < 8) {
            #pragma unroll
            for (int o = 0; o < OUT_DIM; o++) dp[o] += acc[o];
        }
        __syncthreads();
        if (tid < TC * OUT_DIM) {        // 320 threads: one (t,o) each
            float s = drvp[0][tid];
            #pragma unroll
            for (int q = 1; q < 8; q++) s += drvp[q][tid];
            drvp[0][tid] = s;
        }
        __syncthreads();

        // ---- incremental LIF scan by threads 0..9 ----
        if (tid < OUT_DIM) {
            const int o    = tid;
            const int tend = min(TC, NSCAN - t0);
            if (fst == 0) {
                for (int tt = 0; tt < tend; tt++) {
                    float Vn = A_M * V + G_M * I;
                    float In = A_S * I + drvp[0][tt * OUT_DIM + o];
                    if (Vn > 1.0f) { fst = t0 + tt + 1; break; }
                    V = Vn;
                    I = In;
                }
            }
            unsigned m = __ballot_sync(0x3FFu, fst != 0);
            if (tid == 0 && m == 0x3FFu) done_sh = 1;
        }
        __syncthreads();
        if (done_sh) break;              // all 10 neurons spiked: rest of x[b] is dead
    }

    if (tid < OUT_DIM)
        out[b * OUT_DIM + tid] = (fst == 0) ? (float)(STEPS - 1) : (float)fst;
}

extern "C" void kernel_launch(void* const* d_in, const int* in_sizes, int n_in,
                              void* d_out, int out_size)
{
    const float* x = (const float*)d_in[0];   // [512, 784, 200]
    const float* w = (const float*)d_in[1];   // [10, 784]
    float* out = (float*)d_out;               // [512, 10]
    snn_kernel<<<BATCH, 512>>>(x, w, out);
}